// round 5
// baseline (speedup 1.0000x reference)
#include <cuda_runtime.h>
#include <math.h>

#define NEG_SLOPE 0.01f
#define MAXN 100000
#define EMAX 3200000
#define NB_MAX 128
#define HID 64
#define INC 128
#define OUTC 5

typedef unsigned long long ull;

// ---------------- scratch (device globals; no allocation allowed) ----------------
__device__ int   g_w8;                        // 1 if indices are int64, 0 if int32
__device__ int   g_cnt [MAXN];                // in-degree counts
__device__ ull   g_tilestate[NB_MAX];         // decoupled-lookback state
__device__ int   g_off [MAXN + 1];            // CSR row offsets
__device__ int   g_pos [MAXN];                // fill cursors
__device__ __align__(16) int2 g_edge[EMAX];   // (src, coef) grouped by dst
__device__ float g_dinv[MAXN];
__device__ __align__(256) float g_h   [(size_t)MAXN * HID];
__device__ __align__(256) float g_agg [(size_t)MAXN * HID];
__device__ __align__(256) float g_h1  [(size_t)MAXN * HID];
__device__ __align__(256) float g_agg1[(size_t)MAXN * HID];

// ---------------- helpers ----------------
__device__ __forceinline__ int ldidx(const void* p, long long i, int w8) {
    return w8 ? (int)__ldg((const long long*)p + i) : __ldg((const int*)p + i);
}
__device__ __forceinline__ float leaky(float v) { return v > 0.f ? v : NEG_SLOPE * v; }

#define FFMA2(d, a, b, c) \
    asm("fma.rn.f32x2 %0, %1, %2, %3;" : "=l"(d) : "l"(a), "l"(b), "l"(c))
#define MULX2(d, a, b) \
    asm("mul.rn.f32x2 %0, %1, %2;" : "=l"(d) : "l"(a), "l"(b))
#define PACK2(d, lo, hi) \
    asm("mov.b64 %0, {%1, %2};" : "=l"(d) : "f"(lo), "f"(hi))

// ---------------- (1) prep: detect dtype, zero counts + scan state ----------------
__global__ void prep_kernel(const unsigned int* p, int n) {
    int i = blockIdx.x * blockDim.x + threadIdx.x;
    if (i < n) g_cnt[i] = 0;
    if (i < NB_MAX) g_tilestate[i] = 0ULL;
    if (blockIdx.x == 0) {
        __shared__ int nz;
        if (threadIdx.x == 0) nz = 0;
        __syncthreads();
        if (p[2 * threadIdx.x + 1] != 0u) atomicExch(&nz, 1);
        __syncthreads();
        if (threadIdx.x == 0) g_w8 = (nz == 0) ? 1 : 0;
    }
}

// ---------------- (2) count in-degrees ----------------
__global__ void count_kernel(const void* ei, int e32) {
    int w8 = g_w8;
    long long E = w8 ? (e32 >> 1) : e32;
    long long e = (long long)blockIdx.x * blockDim.x + threadIdx.x;
    if (e >= E) return;
    int d = ldidx(ei, E + e, w8);
    atomicAdd(&g_cnt[d], 1);
}

// ---------------- (3) single-pass scan (decoupled lookback) + dinv ----------------
__global__ void scan_kernel(int n) {            // grid nb, block 1024
    __shared__ int sh[1024];
    __shared__ int sh_ex;
    int tile = blockIdx.x;
    int t = threadIdx.x;
    int i = tile * 1024 + t;
    int v = (i < n) ? g_cnt[i] : 0;
    if (i < n) g_dinv[i] = rsqrtf((float)v + 1.0f);   // +1 self loop
    sh[t] = v;
    __syncthreads();
    #pragma unroll
    for (int o = 1; o < 1024; o <<= 1) {
        int u = (t >= o) ? sh[t - o] : 0;
        __syncthreads();
        sh[t] += u;
        __syncthreads();
    }
    int total = sh[1023];                       // block total

    if (t == 0) {
        // publish PARTIAL so successors can make progress
        atomicExch(&g_tilestate[tile], (1ULL << 62) | (unsigned)total);
        int ex = 0;
        for (int p = tile - 1; p >= 0; ) {
            ull st = atomicAdd(&g_tilestate[p], 0ULL);
            ull flag = st >> 62;
            if (flag == 0) { __nanosleep(40); continue; }
            ex += (int)(st & 0xFFFFFFFFULL);
            if (flag == 2ULL) break;            // INCLUSIVE: prefix complete
            p--;
        }
        atomicExch(&g_tilestate[tile], (2ULL << 62) | (unsigned)(ex + total));
        sh_ex = ex;
    }
    __syncthreads();
    int base = sh_ex;
    if (i < n) {
        int off = base + sh[t] - v;             // exclusive
        g_off[i] = off;
        g_pos[i] = off;
        if (i == n - 1) g_off[n] = base + sh[t];
    }
}

// ---------------- (4) fill packed edge records ----------------
__global__ void fill_kernel(const void* ei, int e32) {
    int w8 = g_w8;
    long long E = w8 ? (e32 >> 1) : e32;
    long long e = (long long)blockIdx.x * blockDim.x + threadIdx.x;
    if (e >= E) return;
    int s = ldidx(ei, e, w8);
    int d = ldidx(ei, E + e, w8);
    float c = __ldg(&g_dinv[s]) * __ldg(&g_dinv[d]);
    int p = atomicAdd(&g_pos[d], 1);
    if (p < EMAX) g_edge[p] = make_int2(s, __float_as_int(c));
}

// ---------------- fused GEMM (f32x2 packed FMA) ----------------
template<int K, int LAYER>
__global__ void gemm_kernel(const float* __restrict__ Xext,
                            const float* __restrict__ W,
                            const float* __restrict__ bias,
                            int n)
{
    const int CK = 32;
    __shared__ __align__(16) float Xs2[64][2 * CK];   // duplicated pairs (v,v)
    __shared__ __align__(16) float Ws[CK][64];

    int tid = threadIdx.x;
    int tx = tid & 15;
    int ty = tid >> 4;
    int rb = blockIdx.x * 64;

    ull acc[4][2] = {};

    for (int kc = 0; kc < K; kc += CK) {
        for (int i = tid; i < 64 * CK; i += 256) {
            int r = i >> 5, c = i & 31;
            int row = rb + r;
            float v = 0.f;
            if (row < n) {
                if (LAYER == 1) {
                    v = Xext[(long long)row * K + kc + c];
                } else {
                    v = leaky(g_agg[(long long)row * K + kc + c] + bias[kc + c]);
                }
            }
            float2 vv = make_float2(v, v);
            *(float2*)&Xs2[r][2 * c] = vv;
        }
        for (int i = tid; i < CK * 64; i += 256) {
            int k = i >> 6, c = i & 63;
            Ws[k][c] = W[(long long)(kc + k) * 64 + c];
        }
        __syncthreads();

        #pragma unroll
        for (int kk = 0; kk < CK; kk++) {
            ulonglong2 wv = *(const ulonglong2*)&Ws[kk][tx * 4];
            #pragma unroll
            for (int i = 0; i < 4; i++) {
                ull xx = *(const ull*)&Xs2[ty * 4 + i][2 * kk];
                FFMA2(acc[i][0], xx, wv.x, acc[i][0]);
                FFMA2(acc[i][1], xx, wv.y, acc[i][1]);
            }
        }
        __syncthreads();
    }

    float* H = (LAYER == 1) ? g_h : g_h1;
    #pragma unroll
    for (int i = 0; i < 4; i++) {
        int row = rb + ty * 4 + i;
        if (row >= n) break;
        ulonglong2 hv;
        hv.x = acc[i][0];
        hv.y = acc[i][1];
        *(ulonglong2*)&H[(long long)row * 64 + tx * 4] = hv;
    }
}

// ---------------- CSR pull aggregation: 16 threads per dst row ----------------
// AGG[d] = dinv[d]^2 * H[d] + sum_e coef[e] * H[src[e]]
template<int LAYER>
__global__ void agg_kernel(int n)
{
    int gid = blockIdx.x * blockDim.x + threadIdx.x;
    int row = gid >> 4;
    int t = gid & 15;
    if (row >= n) return;

    const float* __restrict__ H = (LAYER == 1) ? g_h : g_h1;
    float* __restrict__ AGG     = (LAYER == 1) ? g_agg : g_agg1;

    float dd = g_dinv[row];
    float d2 = dd * dd;
    const float4* hp = (const float4*)(H + (size_t)row * 64) + t;
    float4 hv = *hp;
    ull d2p; PACK2(d2p, d2, d2);
    ull a0, a1, xx0, xx1;
    xx0 = *(const ull*)&hv.x;
    xx1 = *(const ull*)&hv.z;
    MULX2(a0, xx0, d2p);
    MULX2(a1, xx1, d2p);

    int beg = g_off[row], end = g_off[row + 1];
    int e = beg;
    for (; e + 2 <= end; e += 2) {
        int2 sc0 = __ldg(&g_edge[e]);
        int2 sc1 = __ldg(&g_edge[e + 1]);
        float4 v0 = *((const float4*)(H + (size_t)sc0.x * 64) + t);
        float4 v1 = *((const float4*)(H + (size_t)sc1.x * 64) + t);
        ull p0, p1;
        float c0 = __int_as_float(sc0.y);
        float c1 = __int_as_float(sc1.y);
        PACK2(p0, c0, c0);
        PACK2(p1, c1, c1);
        FFMA2(a0, *(const ull*)&v0.x, p0, a0);
        FFMA2(a1, *(const ull*)&v0.z, p0, a1);
        FFMA2(a0, *(const ull*)&v1.x, p1, a0);
        FFMA2(a1, *(const ull*)&v1.z, p1, a1);
    }
    if (e < end) {
        int2 sc = __ldg(&g_edge[e]);
        float4 v = *((const float4*)(H + (size_t)sc.x * 64) + t);
        float c = __int_as_float(sc.y);
        ull pc; PACK2(pc, c, c);
        FFMA2(a0, *(const ull*)&v.x, pc, a0);
        FFMA2(a1, *(const ull*)&v.z, pc, a1);
    }

    ulonglong2 outv;
    outv.x = a0;
    outv.y = a1;
    *((ulonglong2*)(AGG + (size_t)row * 64) + t) = outv;
}

// ---------------- final: select rows, activation, tiny MLP + sigmoid ----------------
__global__ void final_kernel(const void* idxp, int nsel,
                             const float* __restrict__ b1,
                             const float* __restrict__ Wm,
                             const float* __restrict__ bm,
                             float* __restrict__ out_hsel,
                             float* __restrict__ out_prob)
{
    int w8 = g_w8;
    int warp = (blockIdx.x * blockDim.x + threadIdx.x) >> 5;
    int lane = threadIdx.x & 31;
    if (warp >= nsel) return;

    int v = ldidx(idxp, warp, w8);
    float a0 = leaky(g_agg1[(long long)v * 64 + lane]      + __ldg(&b1[lane]));
    float a1 = leaky(g_agg1[(long long)v * 64 + lane + 32] + __ldg(&b1[lane + 32]));
    out_hsel[(long long)warp * 64 + lane]      = a0;
    out_hsel[(long long)warp * 64 + lane + 32] = a1;

    #pragma unroll
    for (int j = 0; j < OUTC; j++) {
        float p = a0 * __ldg(&Wm[lane * OUTC + j]) + a1 * __ldg(&Wm[(lane + 32) * OUTC + j]);
        #pragma unroll
        for (int off = 16; off > 0; off >>= 1)
            p += __shfl_down_sync(0xFFFFFFFFu, p, off);
        if (lane == 0)
            out_prob[(long long)warp * OUTC + j] = 1.0f / (1.0f + expf(-(p + __ldg(&bm[j]))));
    }
}

// ---------------- launch (single stream; agg1 is the 6th kernel -> ncu -s 5 hits it) ----------------
extern "C" void kernel_launch(void* const* d_in, const int* in_sizes, int n_in,
                              void* d_out, int out_size)
{
    const float* x   = (const float*)d_in[0];
    const void*  ei  = d_in[1];
    const void*  idx = d_in[2];
    const float* W0  = (const float*)d_in[3];
    const float* b0  = (const float*)d_in[4];
    const float* W1  = (const float*)d_in[5];
    const float* b1  = (const float*)d_in[6];
    const float* Wm  = (const float*)d_in[7];
    const float* bm  = (const float*)d_in[8];

    int n = in_sizes[0] / INC;
    if (n > MAXN) n = MAXN;
    int e32 = in_sizes[1] / 2;                  // edge count if int32
    int nsel = out_size / (HID + OUTC);

    float* out_hsel = (float*)d_out;
    float* out_prob = (float*)d_out + (size_t)nsel * HID;

    int nb = (n + 1023) / 1024;                 // <= NB_MAX

    int gblocks = (n + 63) / 64;
    int ablocks = (int)(((long long)n * 16 + 255) / 256);

    prep_kernel <<<(n + 511) / 512, 512>>>((const unsigned int*)ei, n);   // 1
    count_kernel<<<(e32 + 255) / 256, 256>>>(ei, e32);                    // 2
    scan_kernel <<<nb, 1024>>>(n);                                        // 3
    fill_kernel <<<(e32 + 255) / 256, 256>>>(ei, e32);                    // 4

    gemm_kernel<INC, 1><<<gblocks, 256>>>(x, W0, nullptr, n);             // 5
    agg_kernel<1><<<ablocks, 256>>>(n);                                   // 6  <- profiled
    gemm_kernel<HID, 2><<<gblocks, 256>>>(nullptr, W1, b0, n);            // 7
    agg_kernel<2><<<ablocks, 256>>>(n);                                   // 8
    final_kernel<<<(nsel * 32 + 255) / 256, 256>>>(idx, nsel, b1, Wm, bm, // 9
                                                   out_hsel, out_prob);
}

// round 7
// speedup vs baseline: 1.4397x; 1.4397x over previous
#include <cuda_runtime.h>
#include <math.h>

#define NEG_SLOPE 0.01f
#define MAXN 100000
#define EMAX 3200000
#define NB_MAX 128
#define HID 64
#define INC 128
#define OUTC 5

typedef unsigned long long ull;

// ---------------- scratch (device globals; no allocation allowed) ----------------
__device__ int   g_w8;                        // 1 if indices are int64, 0 if int32
__device__ int   g_cnt [MAXN];                // in-degree counts
__device__ int   g_bsum[NB_MAX];              // block sums for scan
__device__ int   g_off [MAXN + 1];            // CSR row offsets
__device__ int   g_pos [MAXN];                // fill cursors
__device__ int   g_srcs[EMAX];                // src ids grouped by dst
__device__ float g_dinv[MAXN];
__device__ __align__(256) float g_h   [(size_t)MAXN * HID];
__device__ __align__(256) float g_agg [(size_t)MAXN * HID];
__device__ __align__(256) float g_h1  [(size_t)MAXN * HID];
__device__ __align__(256) float g_agg1[(size_t)MAXN * HID];

// ---------------- helpers ----------------
__device__ __forceinline__ int ldidx(const void* p, long long i, int w8) {
    return w8 ? (int)__ldg((const long long*)p + i) : __ldg((const int*)p + i);
}
__device__ __forceinline__ float leaky(float v) { return v > 0.f ? v : NEG_SLOPE * v; }

#define FFMA2(d, a, b, c) \
    asm("fma.rn.f32x2 %0, %1, %2, %3;" : "=l"(d) : "l"(a), "l"(b), "l"(c))
#define MULX2(d, a, b) \
    asm("mul.rn.f32x2 %0, %1, %2;" : "=l"(d) : "l"(a), "l"(b))
#define PACK2(d, lo, hi) \
    asm("mov.b64 %0, {%1, %2};" : "=l"(d) : "f"(lo), "f"(hi))

// ---------------- (1) prep: detect dtype + zero counts ----------------
__global__ void prep_kernel(const unsigned int* p, int n) {
    int i = blockIdx.x * blockDim.x + threadIdx.x;
    if (i < n) g_cnt[i] = 0;
    if (blockIdx.x == 0) {
        __shared__ int nz;
        if (threadIdx.x == 0) nz = 0;
        __syncthreads();
        if (p[2 * threadIdx.x + 1] != 0u) atomicExch(&nz, 1);
        __syncthreads();
        if (threadIdx.x == 0) g_w8 = (nz == 0) ? 1 : 0;
    }
}

// ---------------- (2) count in-degrees ----------------
__global__ void count_kernel(const void* ei, int e32) {
    int w8 = g_w8;
    long long E = w8 ? (e32 >> 1) : e32;
    long long e = (long long)blockIdx.x * blockDim.x + threadIdx.x;
    if (e >= E) return;
    int d = ldidx(ei, E + e, w8);
    atomicAdd(&g_cnt[d], 1);
}

// ---------------- (3,4,5) three-phase scan (dinv fused into A) ----------------
__global__ void scanA_kernel(int n) {           // grid nb, block 1024
    __shared__ int sh[1024];
    int i = blockIdx.x * 1024 + threadIdx.x;
    int v = (i < n) ? g_cnt[i] : 0;
    if (i < n) g_dinv[i] = rsqrtf((float)v + 1.0f);   // +1 self loop
    sh[threadIdx.x] = v;
    __syncthreads();
    for (int s = 512; s > 0; s >>= 1) {
        if (threadIdx.x < s) sh[threadIdx.x] += sh[threadIdx.x + s];
        __syncthreads();
    }
    if (threadIdx.x == 0) g_bsum[blockIdx.x] = sh[0];
}

__global__ void scanB_kernel(int nb) {          // 1 block, NB_MAX threads
    __shared__ int sh[NB_MAX];
    int t = threadIdx.x;
    int v0 = (t < nb) ? g_bsum[t] : 0;
    sh[t] = v0;
    __syncthreads();
    for (int o = 1; o < NB_MAX; o <<= 1) {
        int u = (t >= o) ? sh[t - o] : 0;
        __syncthreads();
        sh[t] += u;
        __syncthreads();
    }
    if (t < nb) g_bsum[t] = sh[t] - v0;         // exclusive
}

__global__ void scanC_kernel(int n) {           // grid nb, block 1024
    __shared__ int sh[1024];
    int b = blockIdx.x, t = threadIdx.x;
    int i = b * 1024 + t;
    int v = (i < n) ? g_cnt[i] : 0;
    sh[t] = v;
    __syncthreads();
    for (int o = 1; o < 1024; o <<= 1) {
        int u = (t >= o) ? sh[t - o] : 0;
        __syncthreads();
        sh[t] += u;
        __syncthreads();
    }
    int base = g_bsum[b];
    if (i < n) {
        int off = base + sh[t] - v;             // exclusive
        g_off[i] = off;
        g_pos[i] = off;
        if (i == n - 1) g_off[n] = base + sh[t];
    }
}

// ---------------- (6) fill: 4-byte src only ----------------
__global__ void fill_kernel(const void* ei, int e32) {
    int w8 = g_w8;
    long long E = w8 ? (e32 >> 1) : e32;
    long long e = (long long)blockIdx.x * blockDim.x + threadIdx.x;
    if (e >= E) return;
    int s = ldidx(ei, e, w8);
    int d = ldidx(ei, E + e, w8);
    int p = atomicAdd(&g_pos[d], 1);
    if (p < EMAX) g_srcs[p] = s;
}

// ---------------- fused GEMM (f32x2 packed FMA) ----------------
// LAYER==1: H = X @ W0            -> g_h
// LAYER==2: A = leaky(g_agg + b0) ; H = A @ W1 -> g_h1
template<int K, int LAYER>
__global__ void gemm_kernel(const float* __restrict__ Xext,
                            const float* __restrict__ W,
                            const float* __restrict__ bias,
                            int n)
{
    const int CK = 32;
    __shared__ __align__(16) float Xs2[64][2 * CK];   // duplicated pairs (v,v)
    __shared__ __align__(16) float Ws[CK][64];

    int tid = threadIdx.x;
    int tx = tid & 15;
    int ty = tid >> 4;
    int rb = blockIdx.x * 64;

    ull acc[4][2] = {};

    for (int kc = 0; kc < K; kc += CK) {
        for (int i = tid; i < 64 * CK; i += 256) {
            int r = i >> 5, c = i & 31;
            int row = rb + r;
            float v = 0.f;
            if (row < n) {
                if (LAYER == 1) {
                    v = Xext[(long long)row * K + kc + c];
                } else {
                    v = leaky(g_agg[(long long)row * K + kc + c] + bias[kc + c]);
                }
            }
            float2 vv = make_float2(v, v);
            *(float2*)&Xs2[r][2 * c] = vv;
        }
        for (int i = tid; i < CK * 64; i += 256) {
            int k = i >> 6, c = i & 63;
            Ws[k][c] = W[(long long)(kc + k) * 64 + c];
        }
        __syncthreads();

        #pragma unroll
        for (int kk = 0; kk < CK; kk++) {
            ulonglong2 wv = *(const ulonglong2*)&Ws[kk][tx * 4];
            #pragma unroll
            for (int i = 0; i < 4; i++) {
                ull xx = *(const ull*)&Xs2[ty * 4 + i][2 * kk];
                FFMA2(acc[i][0], xx, wv.x, acc[i][0]);
                FFMA2(acc[i][1], xx, wv.y, acc[i][1]);
            }
        }
        __syncthreads();
    }

    float* H = (LAYER == 1) ? g_h : g_h1;
    #pragma unroll
    for (int i = 0; i < 4; i++) {
        int row = rb + ty * 4 + i;
        if (row >= n) break;
        ulonglong2 hv;
        hv.x = acc[i][0];
        hv.y = acc[i][1];
        *(ulonglong2*)&H[(long long)row * 64 + tx * 4] = hv;
    }
}

// ---------------- CSR pull aggregation: 16 threads per dst row ----------------
// AGG[d] = dinv[d]^2 * H[d] + sum_e dinv[s]*dinv[d] * H[s]
template<int LAYER>
__global__ void agg_kernel(int n)
{
    int gid = blockIdx.x * blockDim.x + threadIdx.x;
    int row = gid >> 4;
    int t = gid & 15;
    if (row >= n) return;

    const float* __restrict__ H = (LAYER == 1) ? g_h : g_h1;
    float* __restrict__ AGG     = (LAYER == 1) ? g_agg : g_agg1;

    float dd = g_dinv[row];
    float d2 = dd * dd;
    float4 hv = *((const float4*)(H + (size_t)row * 64) + t);
    ull d2p; PACK2(d2p, d2, d2);
    ull a0, a1;
    MULX2(a0, *(const ull*)&hv.x, d2p);
    MULX2(a1, *(const ull*)&hv.z, d2p);

    int beg = g_off[row], end = g_off[row + 1];
    int e = beg;
    for (; e + 2 <= end; e += 2) {
        int s0 = __ldg(&g_srcs[e]);
        int s1 = __ldg(&g_srcs[e + 1]);
        float c0 = __ldg(&g_dinv[s0]) * dd;
        float c1 = __ldg(&g_dinv[s1]) * dd;
        float4 v0 = *((const float4*)(H + (size_t)s0 * 64) + t);
        float4 v1 = *((const float4*)(H + (size_t)s1 * 64) + t);
        ull p0, p1;
        PACK2(p0, c0, c0);
        PACK2(p1, c1, c1);
        FFMA2(a0, *(const ull*)&v0.x, p0, a0);
        FFMA2(a1, *(const ull*)&v0.z, p0, a1);
        FFMA2(a0, *(const ull*)&v1.x, p1, a0);
        FFMA2(a1, *(const ull*)&v1.z, p1, a1);
    }
    if (e < end) {
        int s = __ldg(&g_srcs[e]);
        float c = __ldg(&g_dinv[s]) * dd;
        float4 v = *((const float4*)(H + (size_t)s * 64) + t);
        ull pc; PACK2(pc, c, c);
        FFMA2(a0, *(const ull*)&v.x, pc, a0);
        FFMA2(a1, *(const ull*)&v.z, pc, a1);
    }

    ulonglong2 outv;
    outv.x = a0;
    outv.y = a1;
    *((ulonglong2*)(AGG + (size_t)row * 64) + t) = outv;
}

// ---------------- final: select rows, activation, tiny MLP + sigmoid ----------------
__global__ void final_kernel(const void* idxp, int nsel,
                             const float* __restrict__ b1,
                             const float* __restrict__ Wm,
                             const float* __restrict__ bm,
                             float* __restrict__ out_hsel,
                             float* __restrict__ out_prob)
{
    int w8 = g_w8;
    int warp = (blockIdx.x * blockDim.x + threadIdx.x) >> 5;
    int lane = threadIdx.x & 31;
    if (warp >= nsel) return;

    int v = ldidx(idxp, warp, w8);
    float a0 = leaky(g_agg1[(long long)v * 64 + lane]      + __ldg(&b1[lane]));
    float a1 = leaky(g_agg1[(long long)v * 64 + lane + 32] + __ldg(&b1[lane + 32]));
    out_hsel[(long long)warp * 64 + lane]      = a0;
    out_hsel[(long long)warp * 64 + lane + 32] = a1;

    #pragma unroll
    for (int j = 0; j < OUTC; j++) {
        float p = a0 * __ldg(&Wm[lane * OUTC + j]) + a1 * __ldg(&Wm[(lane + 32) * OUTC + j]);
        #pragma unroll
        for (int off = 16; off > 0; off >>= 1)
            p += __shfl_down_sync(0xFFFFFFFFu, p, off);
        if (lane == 0)
            out_prob[(long long)warp * OUTC + j] = 1.0f / (1.0f + expf(-(p + __ldg(&bm[j]))));
    }
}

// ---------------- launch (single stream) ----------------
extern "C" void kernel_launch(void* const* d_in, const int* in_sizes, int n_in,
                              void* d_out, int out_size)
{
    const float* x   = (const float*)d_in[0];
    const void*  ei  = d_in[1];
    const void*  idx = d_in[2];
    const float* W0  = (const float*)d_in[3];
    const float* b0  = (const float*)d_in[4];
    const float* W1  = (const float*)d_in[5];
    const float* b1  = (const float*)d_in[6];
    const float* Wm  = (const float*)d_in[7];
    const float* bm  = (const float*)d_in[8];

    int n = in_sizes[0] / INC;
    if (n > MAXN) n = MAXN;
    int e32 = in_sizes[1] / 2;                  // edge count if int32
    int nsel = out_size / (HID + OUTC);

    float* out_hsel = (float*)d_out;
    float* out_prob = (float*)d_out + (size_t)nsel * HID;

    int nb = (n + 1023) / 1024;                 // <= NB_MAX

    int gblocks = (n + 63) / 64;
    int ablocks = (int)(((long long)n * 16 + 255) / 256);

    prep_kernel <<<(n + 511) / 512, 512>>>((const unsigned int*)ei, n);   // 1
    count_kernel<<<(e32 + 255) / 256, 256>>>(ei, e32);                    // 2
    scanA_kernel<<<nb, 1024>>>(n);                                        // 3
    scanB_kernel<<<1, NB_MAX>>>(nb);                                      // 4
    scanC_kernel<<<nb, 1024>>>(n);                                        // 5
    fill_kernel <<<(e32 + 255) / 256, 256>>>(ei, e32);                    // 6
    gemm_kernel<INC, 1><<<gblocks, 256>>>(x, W0, nullptr, n);             // 7
    agg_kernel<1><<<ablocks, 256>>>(n);                                   // 8
    gemm_kernel<HID, 2><<<gblocks, 256>>>(nullptr, W1, b0, n);            // 9
    agg_kernel<2><<<ablocks, 256>>>(n);                                   // 10
    final_kernel<<<(nsel * 32 + 255) / 256, 256>>>(idx, nsel, b1, Wm, bm, // 11
                                                   out_hsel, out_prob);
}

// round 8
// speedup vs baseline: 1.5761x; 1.0948x over previous
#include <cuda_runtime.h>
#include <math.h>

#define NEG_SLOPE 0.01f
#define MAXN 100000
#define EMAX 3200000
#define NB_MAX 128
#define HID 64
#define INC 128
#define OUTC 5

typedef unsigned long long ull;

// ---------------- scratch (device globals; zero-initialized at load; every call
// restores the zero-invariant for g_cnt and g_done before exit) ----------------
__device__ int   g_cnt [MAXN];                // in-degree counts (invariant: 0 on entry)
__device__ int   g_done;                      // scanA ticket     (invariant: 0 on entry)
__device__ int   g_bsum[NB_MAX];              // block sums for scan
__device__ int   g_off [MAXN + 1];            // CSR row offsets
__device__ int   g_rank[EMAX];                // per-edge rank within dst bucket
__device__ int   g_srcs[EMAX];                // src ids grouped by dst
__device__ float g_dinv[MAXN];
__device__ __align__(256) float g_h   [(size_t)MAXN * HID];
__device__ __align__(256) float g_agg [(size_t)MAXN * HID];
__device__ __align__(256) float g_h1  [(size_t)MAXN * HID];
__device__ __align__(256) float g_agg1[(size_t)MAXN * HID];

// ---------------- helpers ----------------
__device__ __forceinline__ int ldidx(const void* p, long long i, int w8) {
    return w8 ? (int)__ldg((const long long*)p + i) : __ldg((const int*)p + i);
}
__device__ __forceinline__ float leaky(float v) { return v > 0.f ? v : NEG_SLOPE * v; }

// Per-block dtype detection: int64 little-endian values < 2^31 have all odd
// 32-bit words zero. Check the first 512 pairs (cached in L1/L2, ~free).
// Returns 1 if the buffer is int64, 0 if int32. Uniform across the block.
__device__ __forceinline__ int detect_w8(const void* buf) {
    const unsigned int* p = (const unsigned int*)buf;
    int nonzero = 0;
    for (int j = threadIdx.x; j < 512; j += blockDim.x)
        nonzero |= (int)p[2 * j + 1];
    return __syncthreads_or(nonzero) ? 0 : 1;
}

#define FFMA2(d, a, b, c) \
    asm("fma.rn.f32x2 %0, %1, %2, %3;" : "=l"(d) : "l"(a), "l"(b), "l"(c))

// ---------------- (build 1) count in-degrees + record ranks ----------------
__global__ void count_kernel(const void* ei, int e32) {
    int w8 = detect_w8(ei);
    long long E = w8 ? (e32 >> 1) : e32;
    long long e = (long long)blockIdx.x * blockDim.x + threadIdx.x;
    if (e >= E) return;
    int d = ldidx(ei, E + e, w8);
    g_rank[e] = atomicAdd(&g_cnt[d], 1);
}

// ---------------- (build 2) scanA (tile sums + dinv) with fused scanB ----------------
__global__ void scanAB_kernel(int n, int nb) {  // grid nb, block 1024
    __shared__ int sh[1024];
    int i = blockIdx.x * 1024 + threadIdx.x;
    int v = (i < n) ? g_cnt[i] : 0;
    if (i < n) g_dinv[i] = rsqrtf((float)v + 1.0f);   // +1 self loop
    sh[threadIdx.x] = v;
    __syncthreads();
    for (int s = 512; s > 0; s >>= 1) {
        if (threadIdx.x < s) sh[threadIdx.x] += sh[threadIdx.x + s];
        __syncthreads();
    }
    if (threadIdx.x == 0) g_bsum[blockIdx.x] = sh[0];

    // last arriving block performs the exclusive scan of block sums (scanB)
    __shared__ int s_last;
    __threadfence();
    if (threadIdx.x == 0)
        s_last = (atomicAdd(&g_done, 1) == nb - 1) ? 1 : 0;
    __syncthreads();
    if (s_last) {
        __shared__ int sb[NB_MAX];
        int t = threadIdx.x;
        if (t < NB_MAX) {
            int v0 = (t < nb) ? *(volatile int*)&g_bsum[t] : 0;
            sb[t] = v0;
            __syncthreads();
            for (int o = 1; o < NB_MAX; o <<= 1) {
                int u = (t >= o) ? sb[t - o] : 0;
                __syncthreads();
                sb[t] += u;
                __syncthreads();
            }
            if (t < nb) g_bsum[t] = sb[t] - v0;   // exclusive
            if (t == 0) g_done = 0;               // restore invariant
        } else {
            __syncthreads();
            for (int o = 1; o < NB_MAX; o <<= 1) { __syncthreads(); __syncthreads(); }
        }
    }
}

// ---------------- (build 3) scanC: per-element offsets; re-zero g_cnt ----------------
__global__ void scanC_kernel(int n) {           // grid nb, block 1024
    __shared__ int sh[1024];
    int b = blockIdx.x, t = threadIdx.x;
    int i = b * 1024 + t;
    int v = (i < n) ? g_cnt[i] : 0;
    if (i < n) g_cnt[i] = 0;                    // restore invariant for next call
    sh[t] = v;
    __syncthreads();
    for (int o = 1; o < 1024; o <<= 1) {
        int u = (t >= o) ? sh[t - o] : 0;
        __syncthreads();
        sh[t] += u;
        __syncthreads();
    }
    int base = g_bsum[b];
    if (i < n) {
        g_off[i] = base + sh[t] - v;            // exclusive
        if (i == n - 1) g_off[n] = base + sh[t];
    }
}

// ---------------- (build 4) fill: no atomics (off[d] + rank[e]) ----------------
__global__ void fill_kernel(const void* ei, int e32) {
    int w8 = detect_w8(ei);
    long long E = w8 ? (e32 >> 1) : e32;
    long long e = (long long)blockIdx.x * blockDim.x + threadIdx.x;
    if (e >= E) return;
    int s = ldidx(ei, e, w8);
    int d = ldidx(ei, E + e, w8);
    int pos = __ldg(&g_off[d]) + g_rank[e];
    if (pos < EMAX) g_srcs[pos] = s;
}

// ---------------- fused GEMM (f32x2 packed FMA) ----------------
// LAYER==1: H = X @ W0            -> g_h
// LAYER==2: A = leaky(g_agg + b0) ; H = A @ W1 -> g_h1
template<int K, int LAYER>
__global__ void gemm_kernel(const float* __restrict__ Xext,
                            const float* __restrict__ W,
                            const float* __restrict__ bias,
                            int n)
{
    const int CK = 32;
    __shared__ __align__(16) float Xs2[64][2 * CK];   // duplicated pairs (v,v)
    __shared__ __align__(16) float Ws[CK][64];

    int tid = threadIdx.x;
    int tx = tid & 15;
    int ty = tid >> 4;
    int rb = blockIdx.x * 64;

    ull acc[4][2] = {};

    for (int kc = 0; kc < K; kc += CK) {
        for (int i = tid; i < 64 * CK; i += 256) {
            int r = i >> 5, c = i & 31;
            int row = rb + r;
            float v = 0.f;
            if (row < n) {
                if (LAYER == 1) {
                    v = Xext[(long long)row * K + kc + c];
                } else {
                    v = leaky(g_agg[(long long)row * K + kc + c] + bias[kc + c]);
                }
            }
            float2 vv = make_float2(v, v);
            *(float2*)&Xs2[r][2 * c] = vv;
        }
        for (int i = tid; i < CK * 64; i += 256) {
            int k = i >> 6, c = i & 63;
            Ws[k][c] = W[(long long)(kc + k) * 64 + c];
        }
        __syncthreads();

        #pragma unroll
        for (int kk = 0; kk < CK; kk++) {
            ulonglong2 wv = *(const ulonglong2*)&Ws[kk][tx * 4];
            #pragma unroll
            for (int i = 0; i < 4; i++) {
                ull xx = *(const ull*)&Xs2[ty * 4 + i][2 * kk];
                FFMA2(acc[i][0], xx, wv.x, acc[i][0]);
                FFMA2(acc[i][1], xx, wv.y, acc[i][1]);
            }
        }
        __syncthreads();
    }

    float* H = (LAYER == 1) ? g_h : g_h1;
    #pragma unroll
    for (int i = 0; i < 4; i++) {
        int row = rb + ty * 4 + i;
        if (row >= n) break;
        ulonglong2 hv;
        hv.x = acc[i][0];
        hv.y = acc[i][1];
        *(ulonglong2*)&H[(long long)row * 64 + tx * 4] = hv;
    }
}

// ---------------- CSR pull aggregation: 16 threads per dst row (R3-style) ----------------
// AGG[d] = dinv[d]^2 * H[d] + sum_e dinv[s]*dinv[d] * H[s]
template<int LAYER>
__global__ void agg_kernel(int n)
{
    int gid = blockIdx.x * blockDim.x + threadIdx.x;
    int row = gid >> 4;
    int t = gid & 15;
    if (row >= n) return;

    const float* __restrict__ H = (LAYER == 1) ? g_h : g_h1;
    float* __restrict__ AGG     = (LAYER == 1) ? g_agg : g_agg1;

    float dd = g_dinv[row];
    float d2 = dd * dd;
    float4 hv = *((const float4*)(H + (size_t)row * 64) + t);
    float4 acc = make_float4(hv.x * d2, hv.y * d2, hv.z * d2, hv.w * d2);

    int beg = g_off[row], end = g_off[row + 1];
    for (int e = beg; e < end; e++) {
        int s = __ldg(&g_srcs[e]);
        float c = __ldg(&g_dinv[s]) * dd;
        float4 sv = *((const float4*)(H + (size_t)s * 64) + t);
        acc.x += c * sv.x;
        acc.y += c * sv.y;
        acc.z += c * sv.z;
        acc.w += c * sv.w;
    }
    *((float4*)(AGG + (size_t)row * 64) + t) = acc;
}

// ---------------- final: select rows, activation, tiny MLP + sigmoid ----------------
__global__ void final_kernel(const void* idxp, int nsel,
                             const float* __restrict__ b1,
                             const float* __restrict__ Wm,
                             const float* __restrict__ bm,
                             float* __restrict__ out_hsel,
                             float* __restrict__ out_prob)
{
    int w8 = detect_w8(idxp);
    int warp = (blockIdx.x * blockDim.x + threadIdx.x) >> 5;
    int lane = threadIdx.x & 31;
    if (warp >= nsel) return;

    int v = ldidx(idxp, warp, w8);
    float a0 = leaky(g_agg1[(long long)v * 64 + lane]      + __ldg(&b1[lane]));
    float a1 = leaky(g_agg1[(long long)v * 64 + lane + 32] + __ldg(&b1[lane + 32]));
    out_hsel[(long long)warp * 64 + lane]      = a0;
    out_hsel[(long long)warp * 64 + lane + 32] = a1;

    #pragma unroll
    for (int j = 0; j < OUTC; j++) {
        float p = a0 * __ldg(&Wm[lane * OUTC + j]) + a1 * __ldg(&Wm[(lane + 32) * OUTC + j]);
        #pragma unroll
        for (int off = 16; off > 0; off >>= 1)
            p += __shfl_down_sync(0xFFFFFFFFu, p, off);
        if (lane == 0)
            out_prob[(long long)warp * OUTC + j] = 1.0f / (1.0f + expf(-(p + __ldg(&bm[j]))));
    }
}

// ---------------- launch: CSR build (side stream) overlapped with GEMM1 (main) ----------------
extern "C" void kernel_launch(void* const* d_in, const int* in_sizes, int n_in,
                              void* d_out, int out_size)
{
    const float* x   = (const float*)d_in[0];
    const void*  ei  = d_in[1];
    const void*  idx = d_in[2];
    const float* W0  = (const float*)d_in[3];
    const float* b0  = (const float*)d_in[4];
    const float* W1  = (const float*)d_in[5];
    const float* b1  = (const float*)d_in[6];
    const float* Wm  = (const float*)d_in[7];
    const float* bm  = (const float*)d_in[8];

    int n = in_sizes[0] / INC;
    if (n > MAXN) n = MAXN;
    int e32 = in_sizes[1] / 2;                  // edge count if indices are int32
    int nsel = out_size / (HID + OUTC);

    float* out_hsel = (float*)d_out;
    float* out_prob = (float*)d_out + (size_t)nsel * HID;

    int nb = (n + 1023) / 1024;                 // <= NB_MAX

    int gblocks = (n + 63) / 64;
    int ablocks = (int)(((long long)n * 16 + 255) / 256);
    int eblocks = (e32 + 255) / 256;

    // host-side resources only (reused every call; identical work each call)
    static cudaStream_t s_side = nullptr;
    static cudaEvent_t  e_fork = nullptr, e_join = nullptr;
    if (!s_side) {
        cudaStreamCreateWithFlags(&s_side, cudaStreamNonBlocking);
        cudaEventCreateWithFlags(&e_fork, cudaEventDisableTiming);
        cudaEventCreateWithFlags(&e_join, cudaEventDisableTiming);
    }

    // fork: side stream builds CSR while main stream runs GEMM layer 1
    cudaEventRecord(e_fork, 0);
    cudaStreamWaitEvent(s_side, e_fork, 0);

    count_kernel <<<eblocks, 256, 0, s_side>>>(ei, e32);
    scanAB_kernel<<<nb, 1024, 0, s_side>>>(n, nb);
    scanC_kernel <<<nb, 1024, 0, s_side>>>(n);
    fill_kernel  <<<eblocks, 256, 0, s_side>>>(ei, e32);
    cudaEventRecord(e_join, s_side);

    gemm_kernel<INC, 1><<<gblocks, 256>>>(x, W0, nullptr, n);

    // join: aggregation needs both H (main) and CSR+dinv (side)
    cudaStreamWaitEvent(0, e_join, 0);

    agg_kernel<1><<<ablocks, 256>>>(n);
    gemm_kernel<HID, 2><<<gblocks, 256>>>(nullptr, W1, b0, n);
    agg_kernel<2><<<ablocks, 256>>>(n);
    final_kernel<<<(nsel * 32 + 255) / 256, 256>>>(idx, nsel, b1, Wm, bm,
                                                   out_hsel, out_prob);
}

// round 9
// speedup vs baseline: 1.7922x; 1.1371x over previous
#include <cuda_runtime.h>
#include <math.h>

#define NEG_SLOPE 0.01f
#define MAXN 100000
#define EMAX 3200000
#define NB_MAX 128
#define HID 64
#define INC 128
#define OUTC 5

typedef unsigned long long ull;

// ---------------- scratch (device globals; zero-initialized at load; every call
// restores the zero-invariant for g_cnt and g_tilestate before use) ----------------
__device__ int   g_cnt [MAXN];                // in-degree counts (invariant: 0 on entry)
__device__ ull   g_tilestate[NB_MAX];         // lookback state (zeroed by count each call)
__device__ int   g_off [MAXN + 1];            // CSR row offsets
__device__ int   g_rank[EMAX];                // per-edge rank within dst bucket
__device__ __align__(16) int2 g_edge[EMAX];   // (src, dinv[src]) grouped by dst
__device__ float g_dinv[MAXN];
__device__ __align__(256) float g_h   [(size_t)MAXN * HID];
__device__ __align__(256) float g_agg [(size_t)MAXN * HID];
__device__ __align__(256) float g_h1  [(size_t)MAXN * HID];

// ---------------- helpers ----------------
__device__ __forceinline__ int ldidx(const void* p, long long i, int w8) {
    return w8 ? (int)__ldg((const long long*)p + i) : __ldg((const int*)p + i);
}
__device__ __forceinline__ float leaky(float v) { return v > 0.f ? v : NEG_SLOPE * v; }

// Per-block dtype detection: int64 little-endian values < 2^31 have all odd
// 32-bit words zero. Uniform result across the block.
__device__ __forceinline__ int detect_w8(const void* buf) {
    const unsigned int* p = (const unsigned int*)buf;
    int nonzero = 0;
    for (int j = threadIdx.x; j < 512; j += blockDim.x)
        nonzero |= (int)p[2 * j + 1];
    return __syncthreads_or(nonzero) ? 0 : 1;
}

#define FFMA2(d, a, b, c) \
    asm("fma.rn.f32x2 %0, %1, %2, %3;" : "=l"(d) : "l"(a), "l"(b), "l"(c))

// ---------------- (build 1) count in-degrees + record ranks; reset scan state ----------------
__global__ void count_kernel(const void* ei, int e32) {
    if (blockIdx.x == 0 && threadIdx.x < NB_MAX) g_tilestate[threadIdx.x] = 0ULL;
    int w8 = detect_w8(ei);
    long long E = w8 ? (e32 >> 1) : e32;
    long long e = (long long)blockIdx.x * blockDim.x + threadIdx.x;
    if (e >= E) return;
    int d = ldidx(ei, E + e, w8);
    g_rank[e] = atomicAdd(&g_cnt[d], 1);
}

// ---------------- (build 2) single-pass scan (decoupled lookback) + dinv + cnt reset ----------------
__global__ void scan_kernel(int n) {            // grid nb (<=128, single wave), block 1024
    __shared__ int sh[1024];
    __shared__ int sh_ex;
    int tile = blockIdx.x;
    int t = threadIdx.x;
    int i = tile * 1024 + t;
    int v = (i < n) ? g_cnt[i] : 0;
    if (i < n) {
        g_dinv[i] = rsqrtf((float)v + 1.0f);    // +1 self loop
        g_cnt[i] = 0;                           // restore invariant for next call
    }
    sh[t] = v;
    __syncthreads();
    #pragma unroll
    for (int o = 1; o < 1024; o <<= 1) {
        int u = (t >= o) ? sh[t - o] : 0;
        __syncthreads();
        sh[t] += u;
        __syncthreads();
    }
    int total = sh[1023];

    if (t == 0) {
        atomicExch(&g_tilestate[tile], (1ULL << 62) | (unsigned)total);   // PARTIAL
        int ex = 0;
        for (int p = tile - 1; p >= 0; ) {
            ull st = atomicAdd(&g_tilestate[p], 0ULL);
            ull flag = st >> 62;
            if (flag == 0) { __nanosleep(40); continue; }
            ex += (int)(st & 0xFFFFFFFFULL);
            if (flag == 2ULL) break;            // INCLUSIVE: prefix complete
            p--;
        }
        atomicExch(&g_tilestate[tile], (2ULL << 62) | (unsigned)(ex + total));
        sh_ex = ex;
    }
    __syncthreads();
    int base = sh_ex;
    if (i < n) {
        g_off[i] = base + sh[t] - v;            // exclusive
        if (i == n - 1) g_off[n] = base + sh[t];
    }
}

// ---------------- (build 3) fill: no atomics; payload = (src, dinv[src]) ----------------
__global__ void fill_kernel(const void* ei, int e32) {
    int w8 = detect_w8(ei);
    long long E = w8 ? (e32 >> 1) : e32;
    long long e = (long long)blockIdx.x * blockDim.x + threadIdx.x;
    if (e >= E) return;
    int s = ldidx(ei, e, w8);
    int d = ldidx(ei, E + e, w8);
    int pos = __ldg(&g_off[d]) + g_rank[e];
    float ds = __ldg(&g_dinv[s]);
    if (pos < EMAX) g_edge[pos] = make_int2(s, __float_as_int(ds));
}

// ---------------- fused GEMM (f32x2 packed FMA) ----------------
// LAYER==1: H = X @ W0            -> g_h
// LAYER==2: A = leaky(g_agg + b0) ; H = A @ W1 -> g_h1
template<int K, int LAYER>
__global__ void gemm_kernel(const float* __restrict__ Xext,
                            const float* __restrict__ W,
                            const float* __restrict__ bias,
                            int n)
{
    const int CK = 32;
    __shared__ __align__(16) float Xs2[64][2 * CK];   // duplicated pairs (v,v)
    __shared__ __align__(16) float Ws[CK][64];

    int tid = threadIdx.x;
    int tx = tid & 15;
    int ty = tid >> 4;
    int rb = blockIdx.x * 64;

    ull acc[4][2] = {};

    for (int kc = 0; kc < K; kc += CK) {
        for (int i = tid; i < 64 * CK; i += 256) {
            int r = i >> 5, c = i & 31;
            int row = rb + r;
            float v = 0.f;
            if (row < n) {
                if (LAYER == 1) {
                    v = Xext[(long long)row * K + kc + c];
                } else {
                    v = leaky(g_agg[(long long)row * K + kc + c] + bias[kc + c]);
                }
            }
            float2 vv = make_float2(v, v);
            *(float2*)&Xs2[r][2 * c] = vv;
        }
        for (int i = tid; i < CK * 64; i += 256) {
            int k = i >> 6, c = i & 63;
            Ws[k][c] = W[(long long)(kc + k) * 64 + c];
        }
        __syncthreads();

        #pragma unroll
        for (int kk = 0; kk < CK; kk++) {
            ulonglong2 wv = *(const ulonglong2*)&Ws[kk][tx * 4];
            #pragma unroll
            for (int i = 0; i < 4; i++) {
                ull xx = *(const ull*)&Xs2[ty * 4 + i][2 * kk];
                FFMA2(acc[i][0], xx, wv.x, acc[i][0]);
                FFMA2(acc[i][1], xx, wv.y, acc[i][1]);
            }
        }
        __syncthreads();
    }

    float* H = (LAYER == 1) ? g_h : g_h1;
    #pragma unroll
    for (int i = 0; i < 4; i++) {
        int row = rb + ty * 4 + i;
        if (row >= n) break;
        ulonglong2 hv;
        hv.x = acc[i][0];
        hv.y = acc[i][1];
        *(ulonglong2*)&H[(long long)row * 64 + tx * 4] = hv;
    }
}

// ---------------- layer-1 aggregation: 16 threads per dst row ----------------
// AGG[d] = dinv[d]^2 * H[d] + sum_e dinv[s]*dinv[d] * H[s]
__global__ void agg1_kernel(int n)
{
    int gid = blockIdx.x * blockDim.x + threadIdx.x;
    int row = gid >> 4;
    int t = gid & 15;
    if (row >= n) return;

    float dd = g_dinv[row];
    float d2 = dd * dd;
    float4 hv = *((const float4*)(g_h + (size_t)row * 64) + t);
    float4 acc = make_float4(hv.x * d2, hv.y * d2, hv.z * d2, hv.w * d2);

    int beg = g_off[row], end = g_off[row + 1];
    for (int e = beg; e < end; e++) {
        int2 sc = __ldg(&g_edge[e]);
        float c = __int_as_float(sc.y) * dd;
        float4 sv = *((const float4*)(g_h + (size_t)sc.x * 64) + t);
        acc.x += c * sv.x;
        acc.y += c * sv.y;
        acc.z += c * sv.z;
        acc.w += c * sv.w;
    }
    *((float4*)(g_agg + (size_t)row * 64) + t) = acc;
}

// ---------------- final: fused layer-2 aggregation (selected rows only)
//                  + activation + tiny MLP + sigmoid. One warp per selected row.
__global__ void final_kernel(const void* idxp, int nsel,
                             const float* __restrict__ b1,
                             const float* __restrict__ Wm,
                             const float* __restrict__ bm,
                             float* __restrict__ out_hsel,
                             float* __restrict__ out_prob)
{
    int w8 = detect_w8(idxp);
    int warp = (blockIdx.x * blockDim.x + threadIdx.x) >> 5;
    int lane = threadIdx.x & 31;
    if (warp >= nsel) return;

    int v = ldidx(idxp, warp, w8);

    // aggregate layer 2 for this row only (cols 2*lane, 2*lane+1)
    float dd = g_dinv[v];
    float d2 = dd * dd;
    float2 hv = *((const float2*)(g_h1 + (size_t)v * 64) + lane);
    float2 acc = make_float2(hv.x * d2, hv.y * d2);

    int beg = g_off[v], end = g_off[v + 1];
    for (int e = beg; e < end; e++) {
        int2 sc = __ldg(&g_edge[e]);
        float c = __int_as_float(sc.y) * dd;
        float2 sv = *((const float2*)(g_h1 + (size_t)sc.x * 64) + lane);
        acc.x += c * sv.x;
        acc.y += c * sv.y;
    }

    float2 bb = *((const float2*)b1 + lane);
    float a0 = leaky(acc.x + bb.x);
    float a1 = leaky(acc.y + bb.y);
    *((float2*)(out_hsel + (size_t)warp * 64) + lane) = make_float2(a0, a1);

    #pragma unroll
    for (int j = 0; j < OUTC; j++) {
        float p = a0 * __ldg(&Wm[(2 * lane) * OUTC + j])
                + a1 * __ldg(&Wm[(2 * lane + 1) * OUTC + j]);
        #pragma unroll
        for (int off = 16; off > 0; off >>= 1)
            p += __shfl_down_sync(0xFFFFFFFFu, p, off);
        if (lane == 0)
            out_prob[(size_t)warp * OUTC + j] = 1.0f / (1.0f + expf(-(p + __ldg(&bm[j]))));
    }
}

// ---------------- launch: CSR build (side stream) overlapped with GEMM1 (main) ----------------
extern "C" void kernel_launch(void* const* d_in, const int* in_sizes, int n_in,
                              void* d_out, int out_size)
{
    const float* x   = (const float*)d_in[0];
    const void*  ei  = d_in[1];
    const void*  idx = d_in[2];
    const float* W0  = (const float*)d_in[3];
    const float* b0  = (const float*)d_in[4];
    const float* W1  = (const float*)d_in[5];
    const float* b1  = (const float*)d_in[6];
    const float* Wm  = (const float*)d_in[7];
    const float* bm  = (const float*)d_in[8];

    int n = in_sizes[0] / INC;
    if (n > MAXN) n = MAXN;
    int e32 = in_sizes[1] / 2;                  // edge count if indices are int32
    int nsel = out_size / (HID + OUTC);

    float* out_hsel = (float*)d_out;
    float* out_prob = (float*)d_out + (size_t)nsel * HID;

    int nb = (n + 1023) / 1024;                 // <= NB_MAX (single wave -> lookback safe)

    int gblocks = (n + 63) / 64;
    int ablocks = (int)(((long long)n * 16 + 255) / 256);
    int eblocks = (e32 + 255) / 256;

    // host-side resources only (reused every call; identical work each call)
    static cudaStream_t s_side = nullptr;
    static cudaEvent_t  e_fork = nullptr, e_join = nullptr;
    if (!s_side) {
        cudaStreamCreateWithFlags(&s_side, cudaStreamNonBlocking);
        cudaEventCreateWithFlags(&e_fork, cudaEventDisableTiming);
        cudaEventCreateWithFlags(&e_join, cudaEventDisableTiming);
    }

    // fork: side stream builds CSR while main stream runs GEMM layer 1
    cudaEventRecord(e_fork, 0);
    cudaStreamWaitEvent(s_side, e_fork, 0);

    count_kernel<<<eblocks, 256, 0, s_side>>>(ei, e32);
    scan_kernel <<<nb, 1024, 0, s_side>>>(n);
    fill_kernel <<<eblocks, 256, 0, s_side>>>(ei, e32);
    cudaEventRecord(e_join, s_side);

    gemm_kernel<INC, 1><<<gblocks, 256>>>(x, W0, nullptr, n);

    // join: aggregation needs both H (main) and CSR+dinv (side)
    cudaStreamWaitEvent(0, e_join, 0);

    agg1_kernel<<<ablocks, 256>>>(n);
    gemm_kernel<HID, 2><<<gblocks, 256>>>(nullptr, W1, b0, n);
    final_kernel<<<(nsel * 32 + 255) / 256, 256>>>(idx, nsel, b1, Wm, bm,
                                                   out_hsel, out_prob);
}